// round 13
// baseline (speedup 1.0000x reference)
#include <cuda_runtime.h>
#include <math.h>
#include <stdint.h>

// KoLeoLoss: x [8192, 1024] fp32 -> scalar loss
//   xn = x / max(||x||, 1e-8)
//   I[r] = argmax_{c != r} (xn[r] . xn[c])
//   dist[r] = || xn[r] - xn[I[r]] + 1e-8 ||_2
//   loss = -mean(log(dist + 1e-8))
//
// Pipeline (3 launches):
//   K1: warp-per-row norms + s8 quantized copy (x512); resets g_loss/g_done
//   K2: PERSISTENT int8 mma.m16n8k32 GEMM (296 CTAs, 2/SM) over the 2080
//       upper-triangular 128x128 tiles; cp.async chain is continuous across
//       tile boundaries (next tile's chunks prefetched during the epilogue);
//       dual-sided reduction -> per-(row, col-block) winners (plain stores)
//   K3: warp-per-row top-2 of 64 block winners (shfl butterflies, no smem);
//       fp32 rescore of both (on-the-fly normalize) -> log -> g_loss;
//       last row writes the output scalar (fused finalize)

#define NB 8192
#define ND 1024
#define EPSF 1e-8f
#define QSCALE 512.0f

#define BM 128
#define BN 128
#define BKB 128                      // K-bytes per chunk (128 s8)
#define NCH (ND / BKB)               // 8
#define NST 2
#define NTB (NB / BM)                // 64
#define NTRI (NTB * (NTB + 1) / 2)   // 2080
#define AT_BYTES (BM * BKB)          // 16384
#define STAGE_BYTES (2 * AT_BYTES)   // 32768
#define SB_OFF (NST * STAGE_BYTES)   // 65536: epilogue scratch after stages
#define SMEM_REQ (SB_OFF + 2048)     // 67584 -> still 2 CTAs/SM
#define GRID 296                     // 148 SMs x 2 CTAs

// ---- scratch (static device globals; no allocations allowed) ----
__device__ uint32_t           g_q8[(size_t)NB * ND / 4];    // s8 normalized x512 (8 MB)
__device__ float              g_inv[NB];                    // 1/max(norm, eps)
__device__ unsigned long long g_cand[NB][NTB];              // per-(row, colblock) winner
__device__ double             g_loss;
__device__ unsigned int       g_done;

// monotonic s32 -> u32 key (order-preserving)
__device__ __forceinline__ unsigned int ikey(int s) {
    return (unsigned int)s ^ 0x80000000u;
}

// linear tile index -> upper-triangular (bi, bj), bi <= bj
__device__ __forceinline__ void tile_coords(int L, int& bi, int& bj) {
    int b = (int)floorf((2.f * NTB + 1.f -
                         sqrtf((2.f * NTB + 1.f) * (2.f * NTB + 1.f) - 8.f * L)) * 0.5f);
    if (b < 0) b = 0;
    while (b + 1 <= NTB - 1 && (b + 1) * NTB - ((b + 1) * b) / 2 <= L) b++;
    while (b > 0 && b * NTB - (b * (b - 1)) / 2 > L) b--;
    bi = b;
    bj = b + (L - (b * NTB - (b * (b - 1)) / 2));
}

// ---------------------------------------------------------------------------
// K1: warp-per-row norms + s8 quantization. 8 warps/block, 1024 blocks.
// ---------------------------------------------------------------------------
__global__ __launch_bounds__(256) void normalize_kernel(const float* __restrict__ x) {
    const int lane = threadIdx.x & 31;
    const int wrp  = threadIdx.x >> 5;
    const int row  = blockIdx.x * 8 + wrp;
    if (blockIdx.x == 0 && threadIdx.x == 0) { g_loss = 0.0; g_done = 0u; }

    const float4* xr4 = reinterpret_cast<const float4*>(x + (size_t)row * ND);
    float4 v[8];
    float s = 0.f;
    #pragma unroll
    for (int i = 0; i < 8; i++) {
        v[i] = xr4[i * 32 + lane];
        s = fmaf(v[i].x, v[i].x, s);
        s = fmaf(v[i].y, v[i].y, s);
        s = fmaf(v[i].z, v[i].z, s);
        s = fmaf(v[i].w, v[i].w, s);
    }
    #pragma unroll
    for (int o = 16; o; o >>= 1) s += __shfl_xor_sync(0xffffffffu, s, o);

    const float inv = 1.f / fmaxf(sqrtf(s), EPSF);
    if (lane == 0) g_inv[row] = inv;

    const float qs = inv * QSCALE;
    uint32_t* q8row = g_q8 + (size_t)row * 256;
    #pragma unroll
    for (int i = 0; i < 8; i++) {
        int q0 = max(-127, min(127, __float2int_rn(v[i].x * qs)));
        int q1 = max(-127, min(127, __float2int_rn(v[i].y * qs)));
        int q2 = max(-127, min(127, __float2int_rn(v[i].z * qs)));
        int q3 = max(-127, min(127, __float2int_rn(v[i].w * qs)));
        q8row[i * 32 + lane] =
            (uint32_t)(q0 & 0xff) | ((uint32_t)(q1 & 0xff) << 8) |
            ((uint32_t)(q2 & 0xff) << 16) | ((uint32_t)(q3 & 0xff) << 24);
    }
}

// ---------------------------------------------------------------------------
// K2 helpers
// ---------------------------------------------------------------------------
__device__ __forceinline__ void ldm_x4(uint32_t (&r)[4], uint32_t addr) {
    asm volatile("ldmatrix.sync.aligned.m8n8.x4.shared.b16 {%0,%1,%2,%3}, [%4];"
                 : "=r"(r[0]), "=r"(r[1]), "=r"(r[2]), "=r"(r[3]) : "r"(addr));
}

__device__ __forceinline__ void imma16832(int (&d)[4], const uint32_t (&a)[4],
                                          uint32_t b0, uint32_t b1) {
    asm volatile(
        "mma.sync.aligned.m16n8k32.row.col.s32.s8.s8.s32 "
        "{%0,%1,%2,%3}, {%4,%5,%6,%7}, {%8,%9}, {%0,%1,%2,%3};"
        : "+r"(d[0]), "+r"(d[1]), "+r"(d[2]), "+r"(d[3])
        : "r"(a[0]), "r"(a[1]), "r"(a[2]), "r"(a[3]), "r"(b0), "r"(b1));
}

// stage slot: chunk parity (chunks flow continuously across tiles; NCH even)
__device__ __forceinline__ void load_chunk(uint32_t base, int blkRow, int blkCol,
                                           int tid, int c) {
    const int k0 = c * BKB;
    const uint32_t stage = base + (uint32_t)(c & 1) * STAGE_BYTES;
    const uint8_t* q8 = reinterpret_cast<const uint8_t*>(g_q8);
    #pragma unroll
    for (int i = 0; i < 8; i++) {
        int idx  = i * 256 + tid;        // 0..2047 ; first 1024 = A, rest = B
        int isB  = idx >> 10;
        int lidx = idx & 1023;
        int row  = lidx >> 3;            // 0..127
        int ch   = lidx & 7;             // 16B chunk within 128B row
        const uint8_t* src =
            q8 + (size_t)((isB ? blkCol : blkRow) + row) * ND + k0 + ch * 16;
        uint32_t dst = stage + (uint32_t)isB * AT_BYTES +
                       (uint32_t)(row * 128 + ((ch ^ (row & 7)) * 16));
        asm volatile("cp.async.cg.shared.global [%0], [%1], 16;"
                     :: "r"(dst), "l"(src));
    }
    asm volatile("cp.async.commit_group;" ::: "memory");
}

// ---------------------------------------------------------------------------
// K2: persistent int8 GEMM + dual-sided block-winner epilogue.
// ---------------------------------------------------------------------------
__global__ __launch_bounds__(256, 2) void dot_argmax_mma() {
    extern __shared__ __align__(1024) char dynsm[];
    const int tid  = threadIdx.x;
    const int wid  = tid >> 5;
    const int lane = tid & 31;
    const int wm   = wid & 1;        // 2 M-blocks of 64
    const int wn   = wid >> 1;       // 4 N-blocks of 32

    uint32_t sbase = (uint32_t)__cvta_generic_to_shared(dynsm);
    unsigned long long* sB = reinterpret_cast<unsigned long long*>(dynsm + SB_OFF);

    const int lrow = lane & 15;
    const int chl  = lane >> 4;
    int aRow[4], bRow[2];
    #pragma unroll
    for (int i = 0; i < 4; i++) aRow[i] = wm * 64 + i * 16 + lrow;
    #pragma unroll
    for (int nb = 0; nb < 2; nb++) bRow[nb] = wn * 32 + nb * 16 + lrow;

    const int qr = lane >> 2;
    const int qc = (lane & 3) * 2;

    int L = blockIdx.x;
    int bi, bj;
    tile_coords(L, bi, bj);
    int blkRow = bi * BM;
    int blkCol = bj * BN;

    // cold prologue for the first tile only
    load_chunk(sbase, blkRow, blkCol, tid, 0);
    load_chunk(sbase, blkRow, blkCol, tid, 1);

    for (; L < NTRI; L += GRID) {
        const int Ln = L + GRID;
        const bool hasNext = (Ln < NTRI);
        int nbi = 0, nbj = 0;
        if (hasNext) tile_coords(Ln, nbi, nbj);
        const int nRow = nbi * BM, nCol = nbj * BN;

        int acc[4][4][4];
        #pragma unroll
        for (int i = 0; i < 4; i++)
            #pragma unroll
            for (int j = 0; j < 4; j++)
                #pragma unroll
                for (int q = 0; q < 4; q++) acc[i][j][q] = 0;

        for (int c = 0; c < NCH; c++) {
            // chunks flow continuously: 2 groups in flight at every wait,
            // except the very last chunk of the last tile.
            if (c == NCH - 1 && !hasNext)
                asm volatile("cp.async.wait_group 0;" ::: "memory");
            else
                asm volatile("cp.async.wait_group 1;" ::: "memory");
            __syncthreads();

            const uint32_t stA = sbase + (uint32_t)(c & 1) * STAGE_BYTES;
            const uint32_t stB = stA + AT_BYTES;

            #pragma unroll
            for (int kk = 0; kk < 4; kk++) {   // 4 k32 steps inside 128B chunk
                const int cb = kk * 2 + chl;
                uint32_t aF[4][4];
                #pragma unroll
                for (int i = 0; i < 4; i++) {
                    uint32_t ad = stA + (uint32_t)(aRow[i] * 128 +
                                                   ((cb ^ (aRow[i] & 7)) * 16));
                    ldm_x4(aF[i], ad);
                }
                uint32_t bF[2][4];
                #pragma unroll
                for (int nb = 0; nb < 2; nb++) {
                    uint32_t bd = stB + (uint32_t)(bRow[nb] * 128 +
                                                   ((cb ^ (bRow[nb] & 7)) * 16));
                    ldm_x4(bF[nb], bd);
                }
                #pragma unroll
                for (int i = 0; i < 4; i++) {
                    imma16832(acc[i][0], aF[i], bF[0][0], bF[0][2]);
                    imma16832(acc[i][1], aF[i], bF[0][1], bF[0][3]);
                    imma16832(acc[i][2], aF[i], bF[1][0], bF[1][2]);
                    imma16832(acc[i][3], aF[i], bF[1][1], bF[1][3]);
                }
            }

            __syncthreads();               // stage (c&1) fully consumed
            if (c + 2 < NCH)
                load_chunk(sbase, blkRow, blkCol, tid, c + 2);
            else if (hasNext)              // c==6 -> next chunk0, c==7 -> chunk1
                load_chunk(sbase, nRow, nCol, tid, c + 2 - NCH);
        }

        // ---- epilogue: dual-sided block winners (dedicated smem region,
        //      overlaps with the next tile's in-flight cp.asyncs) ----
        sB[tid] = 0ull;   // [0,128)=row side, [128,256)=col side
        __syncthreads();

        // row side: thread's 8 rows, reduce over its 8 cols
        #pragma unroll
        for (int i = 0; i < 4; i++) {
            #pragma unroll
            for (int h = 0; h < 2; h++) {
                const int lr = wm * 64 + i * 16 + h * 8 + qr;
                const int gr = blkRow + lr;
                unsigned long long best = 0ull;
                #pragma unroll
                for (int j = 0; j < 4; j++) {
                    #pragma unroll
                    for (int e = 0; e < 2; e++) {
                        const int gc = blkCol + wn * 32 + j * 8 + qc + e;
                        unsigned long long key =
                            ((unsigned long long)ikey(acc[i][j][h * 2 + e]) << 32) |
                            (unsigned int)gc;
                        if (gc != gr && key > best) best = key;
                    }
                }
                #pragma unroll
                for (int o = 1; o < 4; o <<= 1) {
                    unsigned long long other = __shfl_xor_sync(0xffffffffu, best, o);
                    if (other > best) best = other;
                }
                if ((lane & 3) == 0) atomicMax(&sB[lr], best);
            }
        }

        // col side (symmetry): thread's 8 cols, reduce over its 8 rows
        #pragma unroll
        for (int j = 0; j < 4; j++) {
            #pragma unroll
            for (int e = 0; e < 2; e++) {
                const int lc = wn * 32 + j * 8 + qc + e;
                const int gc = blkCol + lc;
                unsigned long long best = 0ull;
                #pragma unroll
                for (int i = 0; i < 4; i++) {
                    #pragma unroll
                    for (int h = 0; h < 2; h++) {
                        const int gr = blkRow + wm * 64 + i * 16 + h * 8 + qr;
                        unsigned long long key =
                            ((unsigned long long)ikey(acc[i][j][h * 2 + e]) << 32) |
                            (unsigned int)gr;
                        if (gr != gc && key > best) best = key;
                    }
                }
                #pragma unroll
                for (int o = 4; o < 32; o <<= 1) {
                    unsigned long long other = __shfl_xor_sync(0xffffffffu, best, o);
                    if (other > best) best = other;
                }
                if (lane < 4) atomicMax(&sB[128 + lc], best);
            }
        }

        __syncthreads();
        // every (row, colblock) cell is owned by exactly one tile -> plain stores
        if (tid < 128) {
            g_cand[blkRow + tid][bj] = sB[tid];
        } else if (bi != bj) {   // diagonal: col side duplicates row side; skip
            g_cand[blkCol + (tid - 128)][bi] = sB[tid];
        }
        __syncthreads();         // sB reuse guard for the next iteration

        bi = nbi; bj = nbj; blkRow = nRow; blkCol = nCol;
    }
}

// ---------------------------------------------------------------------------
// K3: warp-per-row top-2 + fp32 rescore (no smem, no __syncthreads).
//     8 warps/block, 1024 blocks. Last finished row writes the output.
// ---------------------------------------------------------------------------
__global__ __launch_bounds__(256) void rescore_kernel(const float* __restrict__ x,
                                                      float* __restrict__ out) {
    const int lane = threadIdx.x & 31;
    const int wrp  = threadIdx.x >> 5;
    const int row  = blockIdx.x * 8 + wrp;

    // 64 candidates, 2 per lane
    const unsigned long long a = g_cand[row][lane];
    const unsigned long long b = g_cand[row][lane + 32];
    unsigned long long mx = a > b ? a : b;

    // top-1 via butterfly (all lanes end with the max)
    unsigned long long m1 = mx;
    #pragma unroll
    for (int o = 16; o; o >>= 1) {
        unsigned long long v = __shfl_xor_sync(0xffffffffu, m1, o);
        if (v > m1) m1 = v;
    }
    // top-2: exclude the unique m1 entry
    unsigned long long sec = (a == m1) ? b : ((b == m1) ? a : mx);
    unsigned long long m2 = sec;
    #pragma unroll
    for (int o = 16; o; o >>= 1) {
        unsigned long long v = __shfl_xor_sync(0xffffffffu, m2, o);
        if (v > m2) m2 = v;
    }

    const int c1 = (int)(unsigned int)(m1 & 0xffffffffull);
    const int c2 = (int)(unsigned int)(m2 & 0xffffffffull);

    // fp32 rescore: normalize on the fly (a_i*inv_a == stored xn numerics)
    const float ia = g_inv[row];
    const float i1 = g_inv[c1];
    const float i2 = g_inv[c2];
    const float4* A  = reinterpret_cast<const float4*>(x + (size_t)row * ND);
    const float4* B1 = reinterpret_cast<const float4*>(x + (size_t)c1 * ND);
    const float4* B2 = reinterpret_cast<const float4*>(x + (size_t)c2 * ND);

    float d1 = 0.f, d2 = 0.f, s1 = 0.f, s2 = 0.f;
    #pragma unroll
    for (int i = 0; i < 8; i++) {
        const int idx = i * 32 + lane;
        float4 av = A[idx], b1v = B1[idx], b2v = B2[idx];
        float ax = av.x * ia, ay = av.y * ia, az = av.z * ia, aw = av.w * ia;
        float px = b1v.x * i1, py = b1v.y * i1, pz = b1v.z * i1, pw = b1v.w * i1;
        float qx = b2v.x * i2, qy = b2v.y * i2, qz = b2v.z * i2, qw = b2v.w * i2;
        d1 = fmaf(ax, px, d1); d1 = fmaf(ay, py, d1);
        d1 = fmaf(az, pz, d1); d1 = fmaf(aw, pw, d1);
        d2 = fmaf(ax, qx, d2); d2 = fmaf(ay, qy, d2);
        d2 = fmaf(az, qz, d2); d2 = fmaf(aw, qw, d2);
        float e;
        e = ax - px + EPSF; s1 = fmaf(e, e, s1);
        e = ay - py + EPSF; s1 = fmaf(e, e, s1);
        e = az - pz + EPSF; s1 = fmaf(e, e, s1);
        e = aw - pw + EPSF; s1 = fmaf(e, e, s1);
        e = ax - qx + EPSF; s2 = fmaf(e, e, s2);
        e = ay - qy + EPSF; s2 = fmaf(e, e, s2);
        e = az - qz + EPSF; s2 = fmaf(e, e, s2);
        e = aw - qw + EPSF; s2 = fmaf(e, e, s2);
    }
    #pragma unroll
    for (int o = 16; o; o >>= 1) {
        d1 += __shfl_xor_sync(0xffffffffu, d1, o);
        d2 += __shfl_xor_sync(0xffffffffu, d2, o);
        s1 += __shfl_xor_sync(0xffffffffu, s1, o);
        s2 += __shfl_xor_sync(0xffffffffu, s2, o);
    }

    if (lane == 0) {
        bool take2 = (d2 > d1) || (d2 == d1 && c2 < c1);  // argmax first-index tiebreak
        float S = take2 ? s2 : s1;
        atomicAdd(&g_loss, (double)logf(sqrtf(S) + EPSF));
        __threadfence();
        unsigned int done = atomicAdd(&g_done, 1u);
        if (done == NB - 1) {
            out[0] = (float)(-g_loss / (double)NB);
        }
    }
}

extern "C" void kernel_launch(void* const* d_in, const int* in_sizes, int n_in,
                              void* d_out, int out_size) {
    const float* x = (const float*)d_in[0];
    float* out = (float*)d_out;

    cudaFuncSetAttribute(dot_argmax_mma,
                         cudaFuncAttributeMaxDynamicSharedMemorySize, SMEM_REQ);

    normalize_kernel<<<NB / 8, 256>>>(x);
    dot_argmax_mma<<<GRID, 256, SMEM_REQ>>>();
    rescore_kernel<<<NB / 8, 256>>>(x, out);
}